// round 7
// baseline (speedup 1.0000x reference)
#include <cuda_runtime.h>
#include <math.h>

#define B_  32
#define S_  50
#define Q_  75
#define T_  128
#define F_  64
#define D_  256
#define KW  5
#define NS  (B_*S_)          // 1600 support samples
#define NQ  (B_*Q_)          // 2400 query samples
#define NTOT (NS+NQ)         // 4000

// Scratch (device globals: allocation-free per harness rules)
__device__ float g_spooled[NS * F_];     // pooled support (400 KB)
__device__ float g_qfeat[NQ * F_];       // pooled queries (600 KB)
__device__ float g_G[F_ * F_];           // Gram, plain row-major (for proto)
__device__ float g_Gp[F_ * F_];          // Gram, packed: [i][j2*2+hi] = G[i][j2 + 32*hi]
__device__ float g_h[B_ * KW * F_];      // h_k = G p_k
__device__ float g_c[B_ * KW];           // c_k = p_k . h_k

// ---------------------------------------------------------------------------
// K1: mean-pool over time, sync-free. 16 samples per 256-thread block.
// thread: sample = blockIdx.x*16 + (tid>>4), column group f4 = tid&15.
// Each thread privately sums 128 float4's (coalesced: warp reads 2x256B/iter).
// ---------------------------------------------------------------------------
__global__ void __launch_bounds__(256) pool_kernel(const float* __restrict__ sx,
                                                   const float* __restrict__ qx) {
    int tid = threadIdx.x;
    int f4  = tid & 15;
    int sn  = blockIdx.x * 16 + (tid >> 4);   // blocks 0..99 support, 100..249 query

    const float4* src;
    float4* dst;
    if (sn < NS) {
        src = reinterpret_cast<const float4*>(sx) + (size_t)sn * (T_ * F_ / 4);
        dst = reinterpret_cast<float4*>(g_spooled) + sn * 16 + f4;
    } else {
        src = reinterpret_cast<const float4*>(qx) + (size_t)(sn - NS) * (T_ * F_ / 4);
        dst = reinterpret_cast<float4*>(g_qfeat) + (sn - NS) * 16 + f4;
    }

    float4 a0 = make_float4(0.f,0.f,0.f,0.f);
    float4 a1 = make_float4(0.f,0.f,0.f,0.f);
    #pragma unroll 8
    for (int t = 0; t < T_; t += 2) {
        float4 v0 = src[t * 16 + f4];
        float4 v1 = src[(t + 1) * 16 + f4];
        a0.x += v0.x; a0.y += v0.y; a0.z += v0.z; a0.w += v0.w;
        a1.x += v1.x; a1.y += v1.y; a1.z += v1.z; a1.w += v1.w;
    }
    const float inv = 1.0f / (float)T_;
    float4 r;
    r.x = (a0.x + a1.x) * inv;
    r.y = (a0.y + a1.y) * inv;
    r.z = (a0.z + a1.z) * inv;
    r.w = (a0.w + a1.w) * inv;
    *dst = r;
}

// ---------------------------------------------------------------------------
// K2: Gram G = W W^T (64x64). Block i computes row i; warp w computes
// j = w*8..w*8+7 via lane-partitioned dots (no __syncthreads).
// Also writes the packed layout used by dist_kernel.
// ---------------------------------------------------------------------------
__global__ void __launch_bounds__(256) gram_kernel(const float* __restrict__ Wm) {
    int i    = blockIdx.x;
    int warp = threadIdx.x >> 5;
    int lane = threadIdx.x & 31;

    float wi[8];
    #pragma unroll
    for (int u = 0; u < 8; u++)
        wi[u] = Wm[i * D_ + lane + 32 * u];

    #pragma unroll
    for (int jj = 0; jj < 8; jj++) {
        int j = warp * 8 + jj;
        const float* wj = Wm + j * D_;
        float s = 0.f;
        #pragma unroll
        for (int u = 0; u < 8; u++)
            s += wi[u] * wj[lane + 32 * u];
        #pragma unroll
        for (int off = 16; off > 0; off >>= 1)
            s += __shfl_xor_sync(0xffffffffu, s, off);
        if (lane == 0) {
            g_G[i * F_ + j] = s;
            g_Gp[i * F_ + (j & 31) * 2 + (j >> 5)] = s;
        }
    }
}

// ---------------------------------------------------------------------------
// K3: 64-dim prototypes + h_k = G p_k + c_k = p_k.h_k.  Block per episode,
// 64 threads (thread = feature f).
// ---------------------------------------------------------------------------
__global__ void __launch_bounds__(64) proto_kernel(const int* __restrict__ y) {
    int b = blockIdx.x;
    int f = threadIdx.x;

    __shared__ int   ys[S_];
    __shared__ float psh[KW][F_];
    __shared__ float csh[KW][F_];

    if (f < S_) ys[f] = y[b * S_ + f];
    __syncthreads();

    float a0=0.f,a1=0.f,a2=0.f,a3=0.f,a4=0.f;
    int   c0=0,c1=0,c2=0,c3=0,c4=0;
    #pragma unroll 10
    for (int s = 0; s < S_; s++) {
        float v = g_spooled[(b * S_ + s) * F_ + f];
        int l = ys[s];
        if (l == 0) { a0 += v; c0++; }
        if (l == 1) { a1 += v; c1++; }
        if (l == 2) { a2 += v; c2++; }
        if (l == 3) { a3 += v; c3++; }
        if (l == 4) { a4 += v; c4++; }
    }
    psh[0][f] = c0 ? a0 / (float)c0 : 0.f;
    psh[1][f] = c1 ? a1 / (float)c1 : 0.f;
    psh[2][f] = c2 ? a2 / (float)c2 : 0.f;
    psh[3][f] = c3 ? a3 / (float)c3 : 0.f;
    psh[4][f] = c4 ? a4 / (float)c4 : 0.f;
    __syncthreads();

    // h[k][f] = sum_i G[i][f] * p[k][i]   (G symmetric => coalesced reads)
    float hk[KW];
    #pragma unroll
    for (int k = 0; k < KW; k++) hk[k] = 0.f;
    for (int i = 0; i < F_; i++) {
        float gi = g_G[i * F_ + f];
        #pragma unroll
        for (int k = 0; k < KW; k++)
            hk[k] += gi * psh[k][i];
    }
    #pragma unroll
    for (int k = 0; k < KW; k++) {
        g_h[(b * KW + k) * F_ + f] = hk[k];
        csh[k][f] = psh[k][f] * hk[k];
    }
    __syncthreads();

    if (f < 32) {
        #pragma unroll
        for (int k = 0; k < KW; k++) {
            float v = csh[k][f] + csh[k][f + 32];
            #pragma unroll
            for (int off = 16; off > 0; off >>= 1)
                v += __shfl_xor_sync(0xffffffffu, v, off);
            if (f == 0) g_c[b * KW + k] = v;
        }
    }
}

// ---------------------------------------------------------------------------
// K4: logits via dist^2 = qGq - 2 q.h_k + c_k.  Warp per query; G (16KB,
// float2-packed), h, c staged in shared; one 64x64 matvec per query.
// ---------------------------------------------------------------------------
__global__ void __launch_bounds__(256) dist_kernel(float* __restrict__ out) {
    int b    = blockIdx.x / 10;
    int blk  = blockIdx.x % 10;
    int warp = threadIdx.x >> 5;
    int lane = threadIdx.x & 31;
    int tid  = threadIdx.x;

    __shared__ float  Gs[F_ * F_];     // packed: Gs[i*64 + j2*2 + hi] ; 16 KB
    __shared__ float  hs[KW * F_];     // 1.25 KB
    __shared__ float  cs[KW];
    __shared__ float  qsh[8][F_];      // 2 KB

    {   // stage G (4096 floats) as float4
        const float4* gsrc = reinterpret_cast<const float4*>(g_Gp);
        float4* gdst = reinterpret_cast<float4*>(Gs);
        #pragma unroll
        for (int u = 0; u < 4; u++) gdst[tid + 256 * u] = gsrc[tid + 256 * u];
        const float* hsrc = g_h + b * KW * F_;
        // KW*F_ = 320 > 256: MUST stride (R6 bug: tail of h was never staged)
        for (int i = tid; i < KW * F_; i += 256) hs[i] = hsrc[i];
        if (tid < KW) cs[tid] = g_c[b * KW + tid];
    }
    __syncthreads();

    int q = blk * 8 + warp;
    if (q >= Q_) return;
    int bq = b * Q_ + q;

    float q0 = g_qfeat[bq * F_ + lane];
    float q1 = g_qfeat[bq * F_ + lane + 32];
    qsh[warp][lane]      = q0;
    qsh[warp][lane + 32] = q1;
    __syncwarp();

    // e = G q  (lane owns columns lane and lane+32 via packed float2)
    float e0 = 0.f, e1 = 0.f;
    const float2* Gp2 = reinterpret_cast<const float2*>(Gs);
    #pragma unroll
    for (int i = 0; i < F_; i++) {
        float qi = qsh[warp][i];
        float2 g = Gp2[i * 32 + lane];
        e0 += qi * g.x;
        e1 += qi * g.y;
    }
    float a = q0 * e0 + q1 * e1;
    #pragma unroll
    for (int off = 16; off > 0; off >>= 1)
        a += __shfl_xor_sync(0xffffffffu, a, off);

    #pragma unroll
    for (int k = 0; k < KW; k++) {
        float s = q0 * hs[k * F_ + lane] + q1 * hs[k * F_ + lane + 32];
        #pragma unroll
        for (int off = 16; off > 0; off >>= 1)
            s += __shfl_xor_sync(0xffffffffu, s, off);
        if (lane == 0)
            out[bq * KW + k] = -sqrtf(fmaxf(a - 2.f * s + cs[k], 0.f));
    }
}

// ---------------------------------------------------------------------------
// Inputs (metadata order): support_x f32, support_y i32, query_x f32, W f32, b f32
// Output: f32 [B*Q, KW] = [2400, 5]
// ---------------------------------------------------------------------------
extern "C" void kernel_launch(void* const* d_in, const int* in_sizes, int n_in,
                              void* d_out, int out_size) {
    const float* sx = (const float*)d_in[0];
    const int*   sy = (const int*)  d_in[1];
    const float* qx = (const float*)d_in[2];
    const float* Wm = (const float*)d_in[3];
    float* out = (float*)d_out;

    pool_kernel <<<NTOT / 16, 256>>>(sx, qx);
    gram_kernel <<<F_,        256>>>(Wm);
    proto_kernel<<<B_,         64>>>(sy);
    dist_kernel <<<B_ * 10,  256>>>(out);
}